// round 12
// baseline (speedup 1.0000x reference)
#include <cuda_runtime.h>

// ---------------------------------------------------------------------------
// RKHS_VNN: 5x (implicit-conv via transposed im2col -> GEMM -> clamp(1+x,0)
// -> maxpool(1,2,2) -> batchnorm) + 3 FC layers.
// Two-GEMM collapse: patches @ (proj^T @ alpha).
// This round: g_col stored K-major ([KP][M]), convgemm rebalanced to the
// 1 B/FMA smem limit (128x64x8 tile, 8x8 micro, conflict-free LDS, prefetch).
// ---------------------------------------------------------------------------

#define CDIV(a,b) (((a)+(b)-1)/(b))

// ---------------- scratch (static device globals; no allocations) ----------
__device__ __align__(16) float g_col[65028096];   // max KP*M (layer2: 648*100352)
__device__ __align__(16) float g_w[1990656];      // max K*O  (layer5: 5184*384)
__device__ __align__(16) float g_pre[9633792];    // max M*O  (layer1: 401408*24)
__device__ __align__(16) float g_actA[2408448];   // max pooled act (layer1 out)
__device__ __align__(16) float g_actB[2408448];
__device__ double g_sum[384];
__device__ double g_sumsq[384];
__device__ __align__(16) float g_fc1[1024];       // 2 x 512
__device__ __align__(16) float g_fc2[512];        // 2 x 256

// ---------------------------------------------------------------------------
// wgemm: g_w[k*O+o] = sum_p proj[p*K+k] * alpha[p*O+o]   (P = 512)
// ---------------------------------------------------------------------------
template<int K, int O>
__global__ __launch_bounds__(256)
void wgemm_kernel(const float* __restrict__ proj, const float* __restrict__ alpha) {
    __shared__ __align__(16) float As[8][64];   // [p][k]
    __shared__ __align__(16) float Bs[8][64];   // [p][o]
    const int k0 = blockIdx.x * 64;
    const int o0 = blockIdx.y * 64;
    const int tid = threadIdx.x;
    const int tx = tid & 15, ty = tid >> 4;
    float acc[4][4] = {};
    for (int p0 = 0; p0 < 512; p0 += 8) {
        #pragma unroll
        for (int e = 0; e < 2; e++) {
            int idx = tid + e * 256;       // 0..511
            int p = idx >> 6, q = idx & 63;
            int gk = k0 + q;
            As[p][q] = (gk < K) ? proj[(p0 + p) * K + gk] : 0.f;
            int go = o0 + q;
            Bs[p][q] = (go < O) ? alpha[(p0 + p) * O + go] : 0.f;
        }
        __syncthreads();
        #pragma unroll
        for (int p = 0; p < 8; p++) {
            float av[4], bv[4];
            #pragma unroll
            for (int i = 0; i < 4; i++) av[i] = As[p][ty * 4 + i];
            #pragma unroll
            for (int j = 0; j < 4; j++) bv[j] = Bs[p][tx * 4 + j];
            #pragma unroll
            for (int i = 0; i < 4; i++)
                #pragma unroll
                for (int j = 0; j < 4; j++)
                    acc[i][j] += av[i] * bv[j];
        }
        __syncthreads();
    }
    #pragma unroll
    for (int i = 0; i < 4; i++) {
        int gk = k0 + ty * 4 + i;
        if (gk >= K) continue;
        #pragma unroll
        for (int j = 0; j < 4; j++) {
            int go = o0 + tx * 4 + j;
            if (go < O) g_w[gk * O + go] = acc[i][j];
        }
    }
}

// ---------------------------------------------------------------------------
// im2col TRANSPOSED: g_col[k*M + m] = x[b, c, d+kd-1, h+kh-1, w+kw-1]
// blockIdx.y = k  (k-decode once per block, uniform); threads sweep m
// -> coalesced reads (consecutive w) and coalesced writes.
// SRC: 0 = external pointer, 1 = g_actA, 2 = g_actB
// ---------------------------------------------------------------------------
template<int C, int HW, int K, int KP, int SRC>
__global__ __launch_bounds__(256)
void im2colT_kernel(const float* __restrict__ xin) {
    const float* __restrict__ src = (SRC == 0) ? xin : ((SRC == 1) ? g_actA : g_actB);
    constexpr int B_ = 2, D_ = 16;
    constexpr int M = B_ * D_ * HW * HW;
    const int k = blockIdx.y;
    int m = blockIdx.x * 256 + threadIdx.x;
    if (m >= M) return;
    float v = 0.f;
    if (k < K) {
        int c  = k / 27;
        int r  = k - c * 27;
        int kd = r / 9;
        int r2 = r - kd * 9;
        int kh = r2 / 3;
        int kw = r2 - kh * 3;
        int w = m % HW;
        int t = m / HW;
        int h = t % HW; t /= HW;
        int d = t % D_;
        int b = t / D_;
        int dd = d + kd - 1, hh = h + kh - 1, ww = w + kw - 1;
        if ((unsigned)dd < (unsigned)D_ && (unsigned)hh < (unsigned)HW && (unsigned)ww < (unsigned)HW)
            v = src[(((b * C + c) * D_ + dd) * HW + hh) * HW + ww];
    }
    g_col[(size_t)k * M + m] = v;
}

// ---------------------------------------------------------------------------
// conv GEMM v2: g_pre[m*N+o] = clamp(1 + sum_k g_col[k*M+m] * g_w[k*N+o], 0)
// Tile 128(m) x 64(n) x 8(k), 128 threads, 8x8 micro (2x4m x 2x4n split),
// register prefetch of next k-slab. Conflict-free LDS, 1 B/FMA.
// ---------------------------------------------------------------------------
template<int M, int N, int KP>
__global__ __launch_bounds__(128)
void convgemm_kernel() {
    __shared__ __align__(16) float As[8][128];  // [k][m]
    __shared__ __align__(16) float Bs[8][64];   // [k][o]
    const int m0 = blockIdx.x * 128;
    const int n0 = blockIdx.y * 64;
    const int tid = threadIdx.x;
    const int tx = tid & 7;      // n group: cols tx*4..+3 and tx*4+32..+35
    const int ty = tid >> 3;     // m group: rows ty*4..+3 and ty*4+64..+67
    float acc[8][8] = {};
    float4 pa[2];
    float  pb[4];

    auto gload = [&](int k0) {
        // A: 8 rows x 128 cols = 256 float4; this thread: f = tid, tid+128
        #pragma unroll
        for (int e = 0; e < 2; e++) {
            int f = tid + e * 128;
            int row = f >> 5;             // 0..7
            int c4 = (f & 31) * 4;        // 0..124
            int gm = m0 + c4;
            const float* p = g_col + (size_t)(k0 + row) * M + gm;
            if (gm + 3 < M) {
                pa[e] = *reinterpret_cast<const float4*>(p);
            } else {
                float4 v = make_float4(0.f, 0.f, 0.f, 0.f);
                if (gm + 0 < M) v.x = p[0];
                if (gm + 1 < M) v.y = p[1];
                if (gm + 2 < M) v.z = p[2];
                if (gm + 3 < M) v.w = p[3];
                pa[e] = v;
            }
        }
        // B: 8 rows x 64 cols = 512 floats; this thread: 4 scalars
        #pragma unroll
        for (int e = 0; e < 4; e++) {
            int idx = tid + e * 128;
            int kk = idx >> 6;            // 0..7
            int oo = idx & 63;
            int go = n0 + oo;
            pb[e] = (go < N) ? g_w[(size_t)(k0 + kk) * N + go] : 0.f;
        }
    };
    auto sstore = [&]() {
        #pragma unroll
        for (int e = 0; e < 2; e++) {
            int f = tid + e * 128;
            int row = f >> 5;
            int c4 = (f & 31) * 4;
            *reinterpret_cast<float4*>(&As[row][c4]) = pa[e];
        }
        #pragma unroll
        for (int e = 0; e < 4; e++) {
            int idx = tid + e * 128;
            Bs[idx >> 6][idx & 63] = pb[e];
        }
    };

    gload(0);
    sstore();
    __syncthreads();

    for (int k0 = 0; k0 < KP; k0 += 8) {
        const bool has_next = (k0 + 8) < KP;
        if (has_next) gload(k0 + 8);
        #pragma unroll
        for (int kk = 0; kk < 8; kk++) {
            float4 a0 = *reinterpret_cast<const float4*>(&As[kk][ty * 4]);
            float4 a1 = *reinterpret_cast<const float4*>(&As[kk][ty * 4 + 64]);
            float4 b0 = *reinterpret_cast<const float4*>(&Bs[kk][tx * 4]);
            float4 b1 = *reinterpret_cast<const float4*>(&Bs[kk][tx * 4 + 32]);
            float av[8] = {a0.x, a0.y, a0.z, a0.w, a1.x, a1.y, a1.z, a1.w};
            float bv[8] = {b0.x, b0.y, b0.z, b0.w, b1.x, b1.y, b1.z, b1.w};
            #pragma unroll
            for (int i = 0; i < 8; i++)
                #pragma unroll
                for (int j = 0; j < 8; j++)
                    acc[i][j] += av[i] * bv[j];
        }
        if (has_next) {
            __syncthreads();
            sstore();
            __syncthreads();
        }
    }

    // epilogue: clamp(1+x, 0), float4 stores (N is always a multiple of 4)
    #pragma unroll
    for (int ih = 0; ih < 2; ih++) {
        #pragma unroll
        for (int i = 0; i < 4; i++) {
            int gm = m0 + ih * 64 + ty * 4 + i;
            if (gm >= M) continue;
            #pragma unroll
            for (int jh = 0; jh < 2; jh++) {
                int gn = n0 + jh * 32 + tx * 4;
                if (gn >= N) continue;
                float4 v;
                v.x = fmaxf(1.f + acc[ih * 4 + i][jh * 4 + 0], 0.f);
                v.y = fmaxf(1.f + acc[ih * 4 + i][jh * 4 + 1], 0.f);
                v.z = fmaxf(1.f + acc[ih * 4 + i][jh * 4 + 2], 0.f);
                v.w = fmaxf(1.f + acc[ih * 4 + i][jh * 4 + 3], 0.f);
                *reinterpret_cast<float4*>(&g_pre[(size_t)gm * N + gn]) = v;
            }
        }
    }
}

// ---------------------------------------------------------------------------
__global__ void zero_stats_kernel() {
    int t = threadIdx.x;
    if (t < 384) { g_sum[t] = 0.0; g_sumsq[t] = 0.0; }
}

// pool (1,2,2) + per-channel sum/sumsq (double atomics). DST: 1=g_actA, 2=g_actB
template<int O, int HW, int DST>
__global__ __launch_bounds__(256)
void pool_stats_kernel() {
    constexpr int B_ = 2, D_ = 16;
    constexpr int HP = HW / 2, WP = HW / 2;
    constexpr int NP = B_ * D_ * HP * WP;
    float* __restrict__ out = (DST == 1) ? g_actA : g_actB;
    const int o = blockIdx.y;
    int i = blockIdx.x * 256 + threadIdx.x;
    float s = 0.f, sq = 0.f;
    if (i < NP) {
        int wp = i % WP;
        int t  = i / WP;
        int hp = t % HP; t /= HP;
        int d  = t % D_;
        int b  = t / D_;
        int m00 = ((b * D_ + d) * HW + 2 * hp) * HW + 2 * wp;
        const float* p0 = g_pre + (size_t)m00 * O + o;
        float v0 = p0[0];
        float v1 = p0[O];
        float v2 = p0[(size_t)HW * O];
        float v3 = p0[(size_t)(HW + 1) * O];
        float v = fmaxf(fmaxf(v0, v1), fmaxf(v2, v3));
        out[(((b * O + o) * D_ + d) * HP + hp) * WP + wp] = v;
        s = v; sq = v * v;
    }
    __shared__ float rs[256], rq[256];
    rs[threadIdx.x] = s; rq[threadIdx.x] = sq;
    __syncthreads();
    #pragma unroll
    for (int st = 128; st > 0; st >>= 1) {
        if (threadIdx.x < st) { rs[threadIdx.x] += rs[threadIdx.x + st]; rq[threadIdx.x] += rq[threadIdx.x + st]; }
        __syncthreads();
    }
    if (threadIdx.x == 0) {
        atomicAdd(&g_sum[o],   (double)rs[0]);
        atomicAdd(&g_sumsq[o], (double)rq[0]);
    }
}

// batchnorm (train-mode batch stats), in place. BUF: 1=g_actA, 2=g_actB
template<int O, int HP, int BUF>
__global__ void bn_kernel(const float* __restrict__ gamma, const float* __restrict__ beta) {
    constexpr int B_ = 2, D_ = 16;
    constexpr int SP = D_ * HP * HP;
    constexpr int total = B_ * O * SP;
    float* __restrict__ act = (BUF == 1) ? g_actA : g_actB;
    int idx = blockIdx.x * blockDim.x + threadIdx.x;
    if (idx >= total) return;
    int o = (idx / SP) % O;
    const double cnt = (double)(B_ * SP);
    double mean = g_sum[o] / cnt;
    double var  = g_sumsq[o] / cnt - mean * mean;
    float inv = rsqrtf((float)var + 1e-5f);
    float m = (float)mean;
    act[idx] = (act[idx] - m) * inv * gamma[o] + beta[o];
}

// ---------------------------------------------------------------------------
// FC layers: block per (output j, batch b), 256-thread dot-product reduction.
// ---------------------------------------------------------------------------
template<int IN, int OUT, int MODE>
__global__ __launch_bounds__(256)
void fc_kernel(const float* __restrict__ w, const float* __restrict__ bias,
               float* __restrict__ dout) {
    const int j = blockIdx.x, b = blockIdx.y;
    const float* __restrict__ in = (MODE == 0) ? g_actA : ((MODE == 1) ? g_fc1 : g_fc2);
    const float4* a  = reinterpret_cast<const float4*>(in + (size_t)b * IN);
    const float4* ww = reinterpret_cast<const float4*>(w + (size_t)j * IN);
    float s = 0.f;
    for (int i = threadIdx.x; i < IN / 4; i += 256) {
        float4 av = a[i], wv = ww[i];
        s += av.x * wv.x + av.y * wv.y + av.z * wv.z + av.w * wv.w;
    }
    __shared__ float red[256];
    red[threadIdx.x] = s;
    __syncthreads();
    #pragma unroll
    for (int st = 128; st > 0; st >>= 1) {
        if (threadIdx.x < st) red[threadIdx.x] += red[threadIdx.x + st];
        __syncthreads();
    }
    if (threadIdx.x == 0) {
        float v = red[0] + bias[j];
        if (MODE == 0)      g_fc1[b * OUT + j] = fmaxf(v, 0.f);
        else if (MODE == 1) g_fc2[b * OUT + j] = fmaxf(v, 0.f);
        else                dout[b * OUT + j] = v;
    }
}

// ---------------------------------------------------------------------------
// Host-side per-layer driver (wgemm hoisted separately)
// ---------------------------------------------------------------------------
template<int CIN, int HW, int K_, int KP_, int COUT, int SRC, int DST>
static void run_layer(const float* xin, const float* gamma, const float* beta) {
    constexpr int M_ = 2 * 16 * HW * HW;
    constexpr int HP = HW / 2;
    constexpr int NP = 2 * 16 * HP * HP;

    im2colT_kernel<CIN, HW, K_, KP_, SRC><<<dim3(CDIV(M_, 256), KP_), 256>>>(xin);
    convgemm_kernel<M_, COUT, KP_><<<dim3(CDIV(M_, 128), CDIV(COUT, 64)), 128>>>();
    zero_stats_kernel<<<1, 384>>>();
    pool_stats_kernel<COUT, HW, DST><<<dim3(CDIV(NP, 256), COUT), 256>>>();
    bn_kernel<COUT, HP, DST><<<CDIV(2 * COUT * 16 * HP * HP, 256), 256>>>(gamma, beta);
}

extern "C" void kernel_launch(void* const* d_in, const int* in_sizes, int n_in,
                              void* d_out, int out_size) {
    const float* x = (const float*)d_in[0];
    const float* p[5], *a[5], *g[5], *q[5];
    for (int i = 0; i < 5; i++) {
        p[i] = (const float*)d_in[1 + 4 * i];
        a[i] = (const float*)d_in[2 + 4 * i];
        g[i] = (const float*)d_in[3 + 4 * i];
        q[i] = (const float*)d_in[4 + 4 * i];
    }
    const float* w1 = (const float*)d_in[21];
    const float* b1 = (const float*)d_in[22];
    const float* w2 = (const float*)d_in[23];
    const float* b2 = (const float*)d_in[24];
    const float* w3 = (const float*)d_in[25];
    const float* b3 = (const float*)d_in[26];
    float* out = (float*)d_out;

    // NOTE: wgemm for layer i writes g_w which layer i's convgemm consumes,
    // so it must run in-sequence with its layer (single g_w buffer).
    // Layer 1 wgemm hoisted first so ncu's -s 5 lands on im2col/convgemm.
    wgemm_kernel<  81,  24><<<dim3(CDIV(  81, 64), CDIV( 24, 64)), 256>>>(p[0], a[0]);
    run_layer<  3, 112,   81,   88,  24, 0, 1>(x, g[0], q[0]);

    wgemm_kernel< 648,  48><<<dim3(CDIV( 648, 64), CDIV( 48, 64)), 256>>>(p[1], a[1]);
    run_layer< 24,  56,  648,  648,  48, 1, 2>(nullptr, g[1], q[1]);

    wgemm_kernel<1296,  96><<<dim3(CDIV(1296, 64), CDIV( 96, 64)), 256>>>(p[2], a[2]);
    run_layer< 48,  28, 1296, 1296,  96, 2, 1>(nullptr, g[2], q[2]);

    wgemm_kernel<2592, 192><<<dim3(CDIV(2592, 64), CDIV(192, 64)), 256>>>(p[3], a[3]);
    run_layer< 96,  14, 2592, 2592, 192, 1, 2>(nullptr, g[3], q[3]);

    wgemm_kernel<5184, 384><<<dim3(CDIV(5184, 64), CDIV(384, 64)), 256>>>(p[4], a[4]);
    run_layer<192,   7, 5184, 5184, 384, 2, 1>(nullptr, g[4], q[4]);

    // classifier head (final activation lives in g_actA, layout == flatten order)
    fc_kernel<55296, 512, 0><<<dim3(512, 2), 256>>>(w1, b1, out);
    fc_kernel<  512, 256, 1><<<dim3(256, 2), 256>>>(w2, b2, out);
    fc_kernel<  256, 101, 2><<<dim3(101, 2), 256>>>(w3, b3, out);
}

// round 16
// speedup vs baseline: 1.2273x; 1.2273x over previous
#include <cuda_runtime.h>

// ---------------------------------------------------------------------------
// RKHS_VNN: 5x (transposed im2col (+fused BN of prev layer) -> raw GEMM
// (per-layer N tile, split-K on deep layers) -> pool kernel that combines
// split-K partials + clamp(1+x,0) + maxpool(1,2,2) + BN stats) + FC head.
// Two-GEMM collapse: patches @ (proj^T @ alpha).
// ---------------------------------------------------------------------------

#define CDIV(a,b) (((a)+(b)-1)/(b))

// ---------------- scratch (static device globals; no allocations) ----------
__device__ __align__(16) float g_col[65028096];   // max KP*M (layer2: 648*100352)
__device__ __align__(16) float g_w[2646016];      // packed W for all 5 layers
__device__ __align__(16) float g_pre[9633792];    // raw conv out / split-K partials
__device__ __align__(16) float g_actA[2408448];   // pooled activations (ping)
__device__ __align__(16) float g_actB[2408448];   // pooled activations (pong)
__device__ double g_sum[384];
__device__ double g_sumsq[384];
__device__ float g_bnscale[384];
__device__ float g_bnshift[384];
__device__ __align__(16) float g_fc1[1024];       // 2 x 512
__device__ __align__(16) float g_fc2[512];        // 2 x 256

// packed g_w offsets (row counts use padded K)
#define W1OFF 0          // 88*24   = 2112
#define W2OFF 2112       // 648*48  = 31104
#define W3OFF 33216      // 1296*96 = 124416
#define W4OFF 157632     // 2592*192= 497664
#define W5OFF 655296     // 5184*384=1990656  -> total 2645952

// ---------------------------------------------------------------------------
// wgemm: g_w[WOFF + k*O + o] = sum_p proj[p*K+k] * alpha[p*O+o]  (P = 512)
// Rows [K, KPAD) are written as zeros.
// ---------------------------------------------------------------------------
template<int K, int O, int KPAD, int WOFF>
__global__ __launch_bounds__(256)
void wgemm_kernel(const float* __restrict__ proj, const float* __restrict__ alpha) {
    __shared__ __align__(16) float As[8][64];   // [p][k]
    __shared__ __align__(16) float Bs[8][64];   // [p][o]
    const int k0 = blockIdx.x * 64;
    const int o0 = blockIdx.y * 64;
    const int tid = threadIdx.x;
    const int tx = tid & 15, ty = tid >> 4;
    float acc[4][4] = {};
    for (int p0 = 0; p0 < 512; p0 += 8) {
        #pragma unroll
        for (int e = 0; e < 2; e++) {
            int idx = tid + e * 256;       // 0..511
            int p = idx >> 6, q = idx & 63;
            int gk = k0 + q;
            As[p][q] = (gk < K) ? proj[(p0 + p) * K + gk] : 0.f;
            int go = o0 + q;
            Bs[p][q] = (go < O) ? alpha[(p0 + p) * O + go] : 0.f;
        }
        __syncthreads();
        #pragma unroll
        for (int p = 0; p < 8; p++) {
            float av[4], bv[4];
            #pragma unroll
            for (int i = 0; i < 4; i++) av[i] = As[p][ty * 4 + i];
            #pragma unroll
            for (int j = 0; j < 4; j++) bv[j] = Bs[p][tx * 4 + j];
            #pragma unroll
            for (int i = 0; i < 4; i++)
                #pragma unroll
                for (int j = 0; j < 4; j++)
                    acc[i][j] += av[i] * bv[j];
        }
        __syncthreads();
    }
    #pragma unroll
    for (int i = 0; i < 4; i++) {
        int gk = k0 + ty * 4 + i;
        if (gk >= KPAD) continue;
        #pragma unroll
        for (int j = 0; j < 4; j++) {
            int go = o0 + tx * 4 + j;
            if (go < O) g_w[WOFF + gk * O + go] = (gk < K) ? acc[i][j] : 0.f;
        }
    }
}

// ---------------------------------------------------------------------------
// im2col TRANSPOSED (+optionally fused BN affine of previous layer):
// g_col[k*M + m] = bn(src[b, c, d+kd-1, h+kh-1, w+kw-1]) or 0 outside/pad-k.
// blockIdx.y = k; threads sweep m -> coalesced reads and writes.
// SRC: 0 = external x (no BN), 1 = g_actA (BN), 2 = g_actB (BN)
// ---------------------------------------------------------------------------
template<int C, int HW, int K, int KP, int SRC>
__global__ __launch_bounds__(256)
void im2colT_kernel(const float* __restrict__ xin) {
    const float* __restrict__ src = (SRC == 0) ? xin : ((SRC == 1) ? g_actA : g_actB);
    constexpr int B_ = 2, D_ = 16;
    constexpr int M = B_ * D_ * HW * HW;
    const int k = blockIdx.y;
    int m = blockIdx.x * 256 + threadIdx.x;
    if (m >= M) return;
    float v = 0.f;
    if (k < K) {
        int c  = k / 27;
        int r  = k - c * 27;
        int kd = r / 9;
        int r2 = r - kd * 9;
        int kh = r2 / 3;
        int kw = r2 - kh * 3;
        int w = m % HW;
        int t = m / HW;
        int h = t % HW; t /= HW;
        int d = t % D_;
        int b = t / D_;
        int dd = d + kd - 1, hh = h + kh - 1, ww = w + kw - 1;
        if ((unsigned)dd < (unsigned)D_ && (unsigned)hh < (unsigned)HW && (unsigned)ww < (unsigned)HW) {
            v = src[(((b * C + c) * D_ + dd) * HW + hh) * HW + ww];
            if (SRC != 0) v = fmaf(v, g_bnscale[c], g_bnshift[c]);
        }
    }
    g_col[(size_t)k * M + m] = v;
}

// ---------------------------------------------------------------------------
// conv GEMM v3 (raw, split-K):
//   g_pre[sp*M*N + m*N + o] = sum_{k in split sp} g_col[k*M+m] * g_w[k*N+o]
// Tile 128(m) x TN(n) x 8(k), THREADS = 4*TN, micro 8x4, register prefetch.
// ---------------------------------------------------------------------------
template<int M, int N, int KP, int TN, int SPLIT, int WOFF>
__global__ __launch_bounds__(4 * TN)
void convgemm_kernel() {
    constexpr int THREADS = 4 * TN;
    constexpr int NT = TN / 4;
    constexpr int KC = KP / SPLIT;
    constexpr int CNTA = (256 + THREADS - 1) / THREADS;
    __shared__ __align__(16) float As[8][128];
    __shared__ __align__(16) float Bs[8][TN];
    const int m0 = blockIdx.x * 128;
    const int n0 = blockIdx.y * TN;
    const int sp = (SPLIT > 1) ? blockIdx.z : 0;
    const int kbase = sp * KC;
    const int tid = threadIdx.x;
    const int tx = tid % NT;      // n group
    const int ty = tid / NT;      // m group (0..15), rows ty*8..+7
    float acc[8][4] = {};
    float4 pa[CNTA];
    float  pb[2];

    auto gload = [&](int k0) {
        #pragma unroll
        for (int e = 0; e < CNTA; e++) {
            int f = tid + e * THREADS;
            if (f < 256) {
                int row = f >> 5;             // 0..7
                int c4 = (f & 31) * 4;        // 0..124
                int gm = m0 + c4;
                const float* p = g_col + (size_t)(k0 + row) * M + gm;
                if (gm + 3 < M) {
                    pa[e] = *reinterpret_cast<const float4*>(p);
                } else {
                    float4 v = make_float4(0.f, 0.f, 0.f, 0.f);
                    if (gm + 0 < M) v.x = p[0];
                    if (gm + 1 < M) v.y = p[1];
                    if (gm + 2 < M) v.z = p[2];
                    pa[e] = v;
                }
            }
        }
        #pragma unroll
        for (int e = 0; e < 2; e++) {
            int idx = tid + e * THREADS;      // < 8*TN
            int kk = idx / TN, oo = idx % TN;
            pb[e] = g_w[WOFF + (size_t)(k0 + kk) * N + (n0 + oo)];
        }
    };
    auto sstore = [&]() {
        #pragma unroll
        for (int e = 0; e < CNTA; e++) {
            int f = tid + e * THREADS;
            if (f < 256) {
                int row = f >> 5;
                int c4 = (f & 31) * 4;
                *reinterpret_cast<float4*>(&As[row][c4]) = pa[e];
            }
        }
        #pragma unroll
        for (int e = 0; e < 2; e++) {
            int idx = tid + e * THREADS;
            Bs[idx / TN][idx % TN] = pb[e];
        }
    };

    gload(kbase);
    sstore();
    __syncthreads();

    for (int k0 = kbase; k0 < kbase + KC; k0 += 8) {
        const bool has_next = (k0 + 8) < (kbase + KC);
        if (has_next) gload(k0 + 8);
        #pragma unroll
        for (int kk = 0; kk < 8; kk++) {
            float4 a0 = *reinterpret_cast<const float4*>(&As[kk][ty * 8]);
            float4 a1 = *reinterpret_cast<const float4*>(&As[kk][ty * 8 + 4]);
            float4 b  = *reinterpret_cast<const float4*>(&Bs[kk][tx * 4]);
            float av[8] = {a0.x, a0.y, a0.z, a0.w, a1.x, a1.y, a1.z, a1.w};
            float bv[4] = {b.x, b.y, b.z, b.w};
            #pragma unroll
            for (int i = 0; i < 8; i++)
                #pragma unroll
                for (int j = 0; j < 4; j++)
                    acc[i][j] += av[i] * bv[j];
        }
        if (has_next) {
            __syncthreads();
            sstore();
            __syncthreads();
        }
    }

    float* dst = g_pre + (size_t)sp * ((size_t)M * N);
    #pragma unroll
    for (int i = 0; i < 8; i++) {
        int gm = m0 + ty * 8 + i;
        if (gm >= M) continue;
        float4 v = make_float4(acc[i][0], acc[i][1], acc[i][2], acc[i][3]);
        *reinterpret_cast<float4*>(&dst[(size_t)gm * N + n0 + tx * 4]) = v;
    }
}

// ---------------------------------------------------------------------------
__global__ void zero_stats_kernel() {
    int t = threadIdx.x;
    if (t < 384) { g_sum[t] = 0.0; g_sumsq[t] = 0.0; }
}

// ---------------------------------------------------------------------------
// pool v2: one block per (b, d, hp). Stages two g_pre h-rows (summing split-K
// partials), applies clamp(1+x,0), maxpools (1,2,2), writes channel-first act,
// accumulates per-channel BN stats. Fully coalesced g_pre reads.
// DST: 1 = g_actA, 2 = g_actB
// ---------------------------------------------------------------------------
template<int O, int HW, int SPLIT, int DST>
__global__ __launch_bounds__(256)
void pool2_kernel() {
    constexpr int B_ = 2, D_ = 16;
    constexpr int HP = HW / 2, WP = HW / 2;
    constexpr int ROWF = HW * O;                      // floats per h-row (=2688)
    constexpr size_t MN = (size_t)(B_ * D_ * HW * HW) * O;
    float* __restrict__ out = (DST == 1) ? g_actA : g_actB;
    __shared__ float sm[2 * ROWF];
    __shared__ double ssum[O], ssq[O];
    const int bidx = blockIdx.x;
    const int hp = bidx % HP;
    const int d  = (bidx / HP) % D_;
    const int b  = bidx / (HP * D_);
    const size_t base = (((size_t)(b * D_ + d) * HW + 2 * hp) * HW) * O;

    for (int o = threadIdx.x; o < O; o += 256) { ssum[o] = 0.0; ssq[o] = 0.0; }
    for (int i = threadIdx.x; i < 2 * ROWF; i += 256) {
        int r = i / ROWF, off = i - r * ROWF;
        size_t gi = base + (size_t)r * ROWF + off;
        float v = g_pre[gi];
        if (SPLIT > 1) {
            #pragma unroll
            for (int s = 1; s < SPLIT; s++) v += g_pre[(size_t)s * MN + gi];
        }
        sm[i] = fmaxf(1.f + v, 0.f);
    }
    __syncthreads();
    for (int j = threadIdx.x; j < WP * O; j += 256) {
        int wp = j / O, o = j - wp * O;
        int c0 = 2 * wp * O + o;
        float v = fmaxf(fmaxf(sm[c0], sm[c0 + O]),
                        fmaxf(sm[ROWF + c0], sm[ROWF + c0 + O]));
        out[((((size_t)b * O + o) * D_ + d) * HP + hp) * WP + wp] = v;
        atomicAdd(&ssum[o], (double)v);
        atomicAdd(&ssq[o],  (double)(v * v));
    }
    __syncthreads();
    for (int o = threadIdx.x; o < O; o += 256) {
        atomicAdd(&g_sum[o],   ssum[o]);
        atomicAdd(&g_sumsq[o], ssq[o]);
    }
}

// stats -> per-channel affine (scale/shift), consumed by next im2col / bnapply
template<int O, int CNT>
__global__ void finalize_kernel(const float* __restrict__ gamma,
                                const float* __restrict__ beta) {
    int o = threadIdx.x;
    if (o >= O) return;
    const double cnt = (double)CNT;
    double mean = g_sum[o] / cnt;
    double var  = g_sumsq[o] / cnt - mean * mean;
    float inv = rsqrtf((float)var + 1e-5f);
    float sc = gamma[o] * inv;
    g_bnscale[o] = sc;
    g_bnshift[o] = beta[o] - (float)mean * sc;
}

// apply BN affine to final activation (g_actA) before the FC head
template<int O, int HP>
__global__ void bnapply_kernel() {
    constexpr int SP = 16 * HP * HP;
    constexpr int total = 2 * O * SP;
    int idx = blockIdx.x * blockDim.x + threadIdx.x;
    if (idx >= total) return;
    int o = (idx / SP) % O;
    g_actA[idx] = fmaf(g_actA[idx], g_bnscale[o], g_bnshift[o]);
}

// ---------------------------------------------------------------------------
// FC layers: block per (output j, batch b), 256-thread dot-product reduction.
// ---------------------------------------------------------------------------
template<int IN, int OUT, int MODE>
__global__ __launch_bounds__(256)
void fc_kernel(const float* __restrict__ w, const float* __restrict__ bias,
               float* __restrict__ dout) {
    const int j = blockIdx.x, b = blockIdx.y;
    const float* __restrict__ in = (MODE == 0) ? g_actA : ((MODE == 1) ? g_fc1 : g_fc2);
    const float4* a  = reinterpret_cast<const float4*>(in + (size_t)b * IN);
    const float4* ww = reinterpret_cast<const float4*>(w + (size_t)j * IN);
    float s = 0.f;
    for (int i = threadIdx.x; i < IN / 4; i += 256) {
        float4 av = a[i], wv = ww[i];
        s += av.x * wv.x + av.y * wv.y + av.z * wv.z + av.w * wv.w;
    }
    __shared__ float red[256];
    red[threadIdx.x] = s;
    __syncthreads();
    #pragma unroll
    for (int st = 128; st > 0; st >>= 1) {
        if (threadIdx.x < st) red[threadIdx.x] += red[threadIdx.x + st];
        __syncthreads();
    }
    if (threadIdx.x == 0) {
        float v = red[0] + bias[j];
        if (MODE == 0)      g_fc1[b * OUT + j] = fmaxf(v, 0.f);
        else if (MODE == 1) g_fc2[b * OUT + j] = fmaxf(v, 0.f);
        else                dout[b * OUT + j] = v;
    }
}

// ---------------------------------------------------------------------------
// Host-side per-layer driver
// ---------------------------------------------------------------------------
template<int CIN, int HW, int K_, int KP_, int COUT, int TN, int SPLIT,
         int SRC, int DST, int WOFF>
static void run_layer(const float* xin, const float* gamma, const float* beta) {
    constexpr int M_ = 2 * 16 * HW * HW;
    constexpr int HP = HW / 2;
    constexpr int CNT = 2 * 16 * HP * HP;

    im2colT_kernel<CIN, HW, K_, KP_, SRC><<<dim3(CDIV(M_, 256), KP_), 256>>>(xin);
    convgemm_kernel<M_, COUT, KP_, TN, SPLIT, WOFF>
        <<<dim3(CDIV(M_, 128), COUT / TN, SPLIT), 4 * TN>>>();
    zero_stats_kernel<<<1, 384>>>();
    pool2_kernel<COUT, HW, SPLIT, DST><<<2 * 16 * HP, 256>>>();
    finalize_kernel<COUT, CNT><<<1, 384>>>(gamma, beta);
}

extern "C" void kernel_launch(void* const* d_in, const int* in_sizes, int n_in,
                              void* d_out, int out_size) {
    const float* x = (const float*)d_in[0];
    const float* p[5], *a[5], *g[5], *q[5];
    for (int i = 0; i < 5; i++) {
        p[i] = (const float*)d_in[1 + 4 * i];
        a[i] = (const float*)d_in[2 + 4 * i];
        g[i] = (const float*)d_in[3 + 4 * i];
        q[i] = (const float*)d_in[4 + 4 * i];
    }
    const float* w1 = (const float*)d_in[21];
    const float* b1 = (const float*)d_in[22];
    const float* w2 = (const float*)d_in[23];
    const float* b2 = (const float*)d_in[24];
    const float* w3 = (const float*)d_in[25];
    const float* b3 = (const float*)d_in[26];
    float* out = (float*)d_out;

    // all 5 collapsed-weight GEMMs up front (packed into g_w)
    wgemm_kernel<  81,  24,   88, W1OFF><<<dim3(2, 1), 256>>>(p[0], a[0]);
    wgemm_kernel< 648,  48,  648, W2OFF><<<dim3(11, 1), 256>>>(p[1], a[1]);
    wgemm_kernel<1296,  96, 1296, W3OFF><<<dim3(21, 2), 256>>>(p[2], a[2]);
    wgemm_kernel<2592, 192, 2592, W4OFF><<<dim3(41, 3), 256>>>(p[3], a[3]);
    wgemm_kernel<5184, 384, 5184, W5OFF><<<dim3(81, 6), 256>>>(p[4], a[4]);

    // 5 poly layers (SRC/DST: 0=x, 1=actA, 2=actB); BN of layer i is fused
    // into layer i+1's im2col via g_bnscale/g_bnshift.
    run_layer<  3, 112,   81,   88,  24, 24, 1, 0, 1, W1OFF>(x,       g[0], q[0]);
    run_layer< 24,  56,  648,  648,  48, 48, 1, 1, 2, W2OFF>(nullptr, g[1], q[1]);
    run_layer< 48,  28, 1296, 1296,  96, 48, 1, 2, 1, W3OFF>(nullptr, g[2], q[2]);
    run_layer< 96,  14, 2592, 2592, 192, 48, 2, 1, 2, W4OFF>(nullptr, g[3], q[3]);
    run_layer<192,   7, 5184, 5184, 384, 48, 4, 2, 1, W5OFF>(nullptr, g[4], q[4]);

    // apply L5 BN, then classifier head (g_actA layout == flatten order)
    bnapply_kernel<384, 3><<<CDIV(2 * 384 * 16 * 9, 256), 256>>>();
    fc_kernel<55296, 512, 0><<<dim3(512, 2), 256>>>(w1, b1, out);
    fc_kernel<  512, 256, 1><<<dim3(256, 2), 256>>>(w2, b2, out);
    fc_kernel<  256, 101, 2><<<dim3(101, 2), 256>>>(w3, b3, out);
}